// round 11
// baseline (speedup 1.0000x reference)
#include <cuda_runtime.h>
#include <cstdint>

// GIN_38216619000492: GINConv (eps=0) + 2-layer MLP.
//   h = x + segment_sum(x[src], dst);  hid = relu(h@W1+b1);  out = hid@W2+b2
// N=50000, E=800000, edge_index int32. MLP via mma.sync tf32 (base sm_100).
// R11: latency-bound diagnosis -> 2 CTAs/SM. 64 rows/CTA, 256 threads,
// 101,632 B smem, B2 staged in two k-halves (acc carried across -> identical
// numerics). Independent barrier domains cover sync/staging latency.

#define D_IN  64
#define D_H   256
#define D_OUT 64
#define NMAX  50000

static __device__ float g_h[(size_t)NMAX * D_IN];
static __device__ float g_B1[17408];   // W1^T tf32: [n=256][k=64] stride 68
static __device__ float g_B2[16896];   // W2^T tf32: [kh=2][n=64][kk=128] stride 132

__device__ __forceinline__ uint32_t f2tf32(float f) {
    uint32_t u;
    asm("cvt.rna.tf32.f32 %0, %1;" : "=r"(u) : "f"(f));
    return u;
}

__device__ __forceinline__ void mma8(float* c, uint32_t a0, uint32_t a1,
                                     uint32_t a2, uint32_t a3,
                                     uint32_t b0, uint32_t b1) {
    asm volatile(
        "mma.sync.aligned.m16n8k8.row.col.f32.tf32.tf32.f32 "
        "{%0,%1,%2,%3}, {%4,%5,%6,%7}, {%8,%9}, {%0,%1,%2,%3};"
        : "+f"(c[0]), "+f"(c[1]), "+f"(c[2]), "+f"(c[3])
        : "r"(a0), "r"(a1), "r"(a2), "r"(a3), "r"(b0), "r"(b1));
}

// ---------------------------------------------------------------------------
// Kernel 1: zero g_h + build tf32 weight images (merged; one launch).
// ---------------------------------------------------------------------------
__global__ void gin_init(const float* __restrict__ W1,
                         const float* __restrict__ W2, int n4) {
    int i = blockIdx.x * blockDim.x + threadIdx.x;
    if (i < n4) ((float4*)g_h)[i] = make_float4(0.f, 0.f, 0.f, 0.f);
    if (i < 16384) {                        // W1[k][n], k<64, n<256
        int k = i >> 8, n = i & 255;
        ((uint32_t*)g_B1)[n * 68 + k] = f2tf32(W1[i]);
    } else if (i < 32768) {                 // W2[k][n], k<256, n<64
        int j = i - 16384;
        int k = j >> 6, n = j & 63;
        int kh = k >> 7, kk = k & 127;
        ((uint32_t*)g_B2)[kh * 8448 + n * 132 + kk] = f2tf32(W2[j]);
    }
}

// ---------------------------------------------------------------------------
// Kernel 2: scatter-add, red.global.add.v4.f32, 16 threads/edge
// (proven; at the LTS byte cap).
// ---------------------------------------------------------------------------
__global__ void gin_scatter(const float* __restrict__ x,
                            const int* __restrict__ ei, int E) {
    int w = blockIdx.x * blockDim.x + threadIdx.x;
    int e = w >> 4;
    if (e >= E) return;
    int c = (w & 15) << 2;
    int src = ei[e];
    int dst = ei[E + e];
    float4 v = *(const float4*)(x + (size_t)src * D_IN + c);
    float* o = g_h + (size_t)dst * D_IN + c;
    asm volatile("red.global.add.v4.f32 [%0], {%1, %2, %3, %4};"
                 :: "l"(o), "f"(v.x), "f"(v.y), "f"(v.z), "f"(v.w)
                 : "memory");
}

// ---------------------------------------------------------------------------
// Kernel 3: fused MLP, tf32 mma.sync. 64 rows/CTA, 8 warps, 2 CTAs/SM.
// GEMM1: warp w -> mq=w&1 (rows [32mq,32mq+32)), nq=w>>1 (cols [64nq,+64)).
// GEMM2: warp w -> mw=w&3 (rows [16mw,+16)),    nh=w>>2 (cols [32nh,+32));
//        k processed in two staged halves, acc carried (identical numerics).
// SMEM word map (101,632 B):
//   phase1: hs @0 [64][68] (4352w), B1 @4352 [256][68] (17408w, ends 21760)
//   phase2: hid @0 [64][260] (16640w), B2H @16640 [64][132] (8448w, ends 25088)
//   b1s @25088 [256], b2s @25344 [64]; total 25408 w.
// ---------------------------------------------------------------------------
#define HS_F    0
#define B1_F    4352
#define HID_F   0
#define B2H_F   16640
#define B1S_F   25088
#define B2S_F   25344
#define SMEM_BYTES (25408 * 4)

__global__ __launch_bounds__(256, 2)
void gin_mlp(const float* __restrict__ x,
             const float* __restrict__ b1, const float* __restrict__ b2,
             float* __restrict__ out, int N) {
    extern __shared__ float s[];
    uint32_t* su = (uint32_t*)s;

    const int t = threadIdx.x;
    const int w = t >> 5;
    const int lane = t & 31;
    const int g = lane >> 2;
    const int tg = lane & 3;
    const int row0 = blockIdx.x * 64;

    // ---- Stage B1, hs, biases ----
    {
        const float4* g1 = (const float4*)g_B1;
        float4* s1 = (float4*)(s + B1_F);
        #pragma unroll 4
        for (int i = t; i < 4352; i += 256) s1[i] = g1[i];
        if (t < 64) ((float4*)(s + B1S_F))[t] = ((const float4*)b1)[t];
        if (t < 16) ((float4*)(s + B2S_F))[t] = ((const float4*)b2)[t];
    }
    #pragma unroll 4
    for (int i = t; i < 1024; i += 256) {      // 64 rows x 16 float4
        int r = i >> 4, k4 = (i & 15) << 2;
        float4 v = make_float4(0.f, 0.f, 0.f, 0.f);
        int gr = row0 + r;
        if (gr < N) {
            float4 xv = *(const float4*)(x   + (size_t)gr * D_IN + k4);
            float4 hv = *(const float4*)(g_h + (size_t)gr * D_IN + k4);
            v = make_float4(xv.x + hv.x, xv.y + hv.y, xv.z + hv.z, xv.w + hv.w);
        }
        uint4 u = make_uint4(f2tf32(v.x), f2tf32(v.y), f2tf32(v.z), f2tf32(v.w));
        *(uint4*)(s + HS_F + r * 68 + k4) = u;
    }
    __syncthreads();

    // ---- GEMM1: warp = rows [32mq,32mq+32) x cols [64nq,64nq+64) ----
    const int mq = w & 1;
    const int nq = w >> 1;
    float acc[2][8][4];
    #pragma unroll
    for (int b = 0; b < 2; b++)
        #pragma unroll
        for (int nt = 0; nt < 8; nt++)
            #pragma unroll
            for (int j = 0; j < 4; j++) acc[b][nt][j] = 0.f;

    {
        const uint32_t* alo0 = su + HS_F + (32 * mq + g) * 68;
        const uint32_t* ahi0 = alo0 + 8 * 68;
        const uint32_t* alo1 = alo0 + 16 * 68;
        const uint32_t* ahi1 = alo0 + 24 * 68;
        const uint32_t* Bb = su + B1_F + (nq * 64 + g) * 68;
        #pragma unroll
        for (int ks = 0; ks < 8; ks++) {
            int kb = ks * 8;
            uint32_t a0[2], a1[2], a2[2], a3[2];
            a0[0] = alo0[kb + tg];     a1[0] = ahi0[kb + tg];
            a2[0] = alo0[kb + tg + 4]; a3[0] = ahi0[kb + tg + 4];
            a0[1] = alo1[kb + tg];     a1[1] = ahi1[kb + tg];
            a2[1] = alo1[kb + tg + 4]; a3[1] = ahi1[kb + tg + 4];
            #pragma unroll
            for (int c4 = 0; c4 < 2; c4++) {
                uint32_t bv[4][2];
                #pragma unroll
                for (int q = 0; q < 4; q++) {
                    int ntl = c4 * 4 + q;
                    bv[q][0] = Bb[ntl * 8 * 68 + kb + tg];
                    bv[q][1] = Bb[ntl * 8 * 68 + kb + tg + 4];
                }
                #pragma unroll
                for (int q = 0; q < 4; q++) {
                    mma8(acc[0][c4 * 4 + q], a0[0], a1[0], a2[0], a3[0], bv[q][0], bv[q][1]);
                    mma8(acc[1][c4 * 4 + q], a0[1], a1[1], a2[1], a3[1], bv[q][0], bv[q][1]);
                }
            }
        }
    }
    __syncthreads();   // hs/B1 reads done; hid/B2H may overlay them

    // ---- Epilogue 1: hid = tf32(relu(D1 + b1)) ----
    {
        #pragma unroll
        for (int b = 0; b < 2; b++) {
            int r_lo = 32 * mq + 16 * b + g;
            float* h_lo = s + HID_F + r_lo * 260;
            float* h_hi = h_lo + 8 * 260;
            #pragma unroll
            for (int ntl = 0; ntl < 8; ntl++) {
                int col = (nq * 8 + ntl) * 8 + 2 * tg;
                float bb0 = s[B1S_F + col], bb1 = s[B1S_F + col + 1];
                uint2 u0, u1;
                u0.x = f2tf32(fmaxf(acc[b][ntl][0] + bb0, 0.f));
                u0.y = f2tf32(fmaxf(acc[b][ntl][1] + bb1, 0.f));
                u1.x = f2tf32(fmaxf(acc[b][ntl][2] + bb0, 0.f));
                u1.y = f2tf32(fmaxf(acc[b][ntl][3] + bb1, 0.f));
                *(uint2*)(h_lo + col) = u0;
                *(uint2*)(h_hi + col) = u1;
            }
        }
    }
    // ---- Stage B2 half 0 (region disjoint from hid) ----
    {
        const float4* gh = (const float4*)g_B2;
        float4* sh = (float4*)(s + B2H_F);
        #pragma unroll 4
        for (int i = t; i < 2112; i += 256) sh[i] = gh[i];
    }
    __syncthreads();

    // ---- GEMM2 (k-half 0): rows [16mw,+16) x cols [32nh,+32) ----
    const int mw = w & 3;
    const int nh = w >> 2;
    float acc2[4][4];
    #pragma unroll
    for (int nt = 0; nt < 4; nt++)
        #pragma unroll
        for (int j = 0; j < 4; j++) acc2[nt][j] = 0.f;

    #pragma unroll
    for (int kh = 0; kh < 2; kh++) {
        if (kh == 1) {
            __syncthreads();    // B2H half-0 reads done
            const float4* gh = (const float4*)(g_B2 + 8448);
            float4* sh = (float4*)(s + B2H_F);
            #pragma unroll 4
            for (int i = t; i < 2112; i += 256) sh[i] = gh[i];
            __syncthreads();
        }
        const uint32_t* arow_lo = su + HID_F + (16 * mw + g) * 260 + kh * 128;
        const uint32_t* arow_hi = arow_lo + 8 * 260;
        const uint32_t* Bb = su + B2H_F + (nh * 32 + g) * 132;
        #pragma unroll 4
        for (int ks = 0; ks < 16; ks++) {
            int kb = ks * 8;
            uint32_t a0 = arow_lo[kb + tg];
            uint32_t a1 = arow_hi[kb + tg];
            uint32_t a2 = arow_lo[kb + tg + 4];
            uint32_t a3 = arow_hi[kb + tg + 4];
            uint32_t bv[4][2];
            #pragma unroll
            for (int q = 0; q < 4; q++) {
                bv[q][0] = Bb[q * 8 * 132 + kb + tg];
                bv[q][1] = Bb[q * 8 * 132 + kb + tg + 4];
            }
            #pragma unroll
            for (int q = 0; q < 4; q++)
                mma8(acc2[q], a0, a1, a2, a3, bv[q][0], bv[q][1]);
        }
    }

    // ---- Epilogue 2: out = D2 + b2 (fp32) ----
    {
        int gr_lo = row0 + 16 * mw + g;
        int gr_hi = gr_lo + 8;
        #pragma unroll
        for (int ntl = 0; ntl < 4; ntl++) {
            int col = nh * 32 + ntl * 8 + 2 * tg;
            float bb0 = s[B2S_F + col], bb1 = s[B2S_F + col + 1];
            if (gr_lo < N) {
                float2 v = make_float2(acc2[ntl][0] + bb0, acc2[ntl][1] + bb1);
                *(float2*)(out + (size_t)gr_lo * D_OUT + col) = v;
            }
            if (gr_hi < N) {
                float2 v = make_float2(acc2[ntl][2] + bb0, acc2[ntl][3] + bb1);
                *(float2*)(out + (size_t)gr_hi * D_OUT + col) = v;
            }
        }
    }
}

// ---------------------------------------------------------------------------
// Launch. Inputs: x[f32], edge_index[i32 2xE], W1, b1, W2, b2.
// ---------------------------------------------------------------------------
extern "C" void kernel_launch(void* const* d_in, const int* in_sizes, int n_in,
                              void* d_out, int out_size) {
    const float* x  = (const float*)d_in[0];
    const int*   ei = (const int*)d_in[1];
    const float* W1 = (const float*)d_in[2];
    const float* b1 = (const float*)d_in[3];
    const float* W2 = (const float*)d_in[4];
    const float* b2 = (const float*)d_in[5];
    float* out = (float*)d_out;

    const int N = in_sizes[0] / D_IN;   // 50000
    const int E = in_sizes[1] / 2;      // 800000

    cudaFuncSetAttribute(gin_mlp, cudaFuncAttributeMaxDynamicSharedMemorySize,
                         SMEM_BYTES);

    int n4 = N * (D_IN / 4);
    gin_init<<<(n4 + 255) / 256, 256>>>(W1, W2, n4);

    int work = E * 16;
    gin_scatter<<<(work + 255) / 256, 256>>>(x, ei, E);

    gin_mlp<<<(N + 63) / 64, 256, SMEM_BYTES>>>(x, b1, b2, out, N);
}